// round 8
// baseline (speedup 1.0000x reference)
#include <cuda_runtime.h>
#include <math.h>
#include <stdint.h>

// Problem constants
#define SIG_LEN   131072
#define NW        4
#define ROWS      256
#define T_OUT     131166
#define SPLIT     8
#define CHK       16384               // input samples owned per block
#define SS        2048                // input samples per scan step

// Skew: conflict-free for 32B/64B-strided LDS.128 (diagonal bank rotation)
#define MP(i) ((i) + ((((i) >> 5)) << 2))

typedef unsigned long long ull;

__device__ float g_filt[2][4][16];    // [lp/hp][wavelet][tap]

// ---------------------------------------------------------------------------
// Filter constraint (fp32): pad->rfft(64)->gauss weight->irfft->trunc->norm*sqrt2
// ---------------------------------------------------------------------------
__global__ void constrain_kernel(const float* __restrict__ low,
                                 const float* __restrict__ high) {
    __shared__ float ctab[64];
    __shared__ float vals[128];
    const int tid = threadIdx.x;                 // 0..127
    if (tid < 64) ctab[tid] = cosf(2.0f * (float)M_PI * (float)tid / 64.0f);
    __syncthreads();

    const int bank = tid >> 6;                   // 0 = lp, 1 = hp
    const int n    = (tid >> 4) & 3;             // wavelet
    const int j    = tid & 15;                   // output tap
    const float* src = bank ? high : low;

    const float target = ((float)n + 0.5f) / (float)NW * 0.5f + (bank ? 0.5f : 0.0f);
    const float inv_width = (float)NW;

    float w[33];
    #pragma unroll
    for (int f = 0; f <= 32; f++) {
        float d = ((float)f / 32.0f - target) * inv_width;
        w[f] = expf(-d * d);
    }

    float acc = 0.0f;
    for (int k = 0; k < 16; k++) {
        int dm = j - k + 64;
        float c = w[0];
        #pragma unroll
        for (int f = 1; f <= 31; f++)
            c = fmaf(2.0f * w[f], ctab[(dm * f) & 63], c);
        c = fmaf(w[32], ctab[(dm * 32) & 63], c);
        acc = fmaf(src[n * 16 + k], c, acc);
    }
    acc *= (1.0f / 64.0f);

    vals[tid] = acc;
    __syncthreads();
    float ss = 0.0f;
    const int base = tid & ~15;
    #pragma unroll
    for (int m = 0; m < 16; m++) { float v = vals[base + m]; ss = fmaf(v, v, ss); }
    float nrm = sqrtf(ss);
    if (nrm < 1e-12f) nrm = 1e-12f;
    g_filt[bank][n][j] = acc / nrm * 1.41421356237309515f;
}

// ---------------------------------------------------------------------------
__device__ __forceinline__ ull fma2(ull a, ull b, ull c) {
    ull d;
    asm("fma.rn.f32x2 %0, %1, %2, %3;" : "=l"(d) : "l"(a), "l"(b), "l"(c));
    return d;
}
__device__ __forceinline__ float hsum2(ull a) {
    float2 v = *reinterpret_cast<float2*>(&a);
    return v.x + v.y;
}

// Shared-memory arena (floats). Step phase: skewed s_in0/1, skewed s_l1A/B,
// linear s_a2. Tail overlays linear L3/L4/L5 on the s_in/s_l1 region.
#define OFF_IN0 0      // skewed, MP(2063)=2319 -> 2320
#define OFF_IN1 2320
#define OFF_L1A 4640   // skewed, MP(1039)=1167 -> 1168
#define OFF_L1B 5808
#define OFF_A2  6976   // linear, 4656 floats
#define ARENA   11632
// tail overlay (linear)
#define OFF_L3  0      // 2208 floats
#define OFF_L4  2208   // 1120 floats
#define OFF_L5  3328   // 576 floats

// ---------------------------------------------------------------------------
// Level-1 pass: 1024 outputs, 4 per thread, skewed src/dst.
// Window for output q0+o = src floats [2q0+2o .. 2q0+2o+15] (pairs P[o..o+7]).
// Echo: outputs 1009..1023 also written to next buffer's head [0..14].
// ---------------------------------------------------------------------------
template<bool DET, bool MASK>
__device__ __forceinline__ void l1_pass(const float* __restrict__ src,
                                        float* __restrict__ dst,
                                        float* __restrict__ nxt,
                                        float* __restrict__ det,
                                        int hi, const ull* fa, const ull* fd,
                                        int tid)
{
    const int q0 = 4 * tid;
    const int b0 = 2 * q0;
    ull P[11];
    #pragma unroll
    for (int k = 0; k < 5; k++) {
        ulonglong2 v = *(const ulonglong2*)(src + MP(b0 + 4 * k));
        P[2 * k] = v.x; P[2 * k + 1] = v.y;
    }
    P[10] = *(const ull*)(src + MP(b0 + 20));

    ull aa[4] = {0ull, 0ull, 0ull, 0ull};
    #pragma unroll
    for (int m = 0; m < 8; m++) {
        #pragma unroll
        for (int o = 0; o < 4; o++) aa[o] = fma2(fa[m], P[o + m], aa[o]);
    }
    float ra[4];
    #pragma unroll
    for (int o = 0; o < 4; o++) ra[o] = hsum2(aa[o]);
    #pragma unroll
    for (int o = 0; o < 4; o++) dst[MP(15 + q0 + o)] = ra[o];
    if (!MASK) {
        #pragma unroll
        for (int o = 0; o < 4; o++) {
            int e = q0 + o - 1009;
            if (e >= 0) nxt[e] = ra[o];          // head region: MP(e)=e
        }
    }
    if (DET) {
        ull dd[4] = {0ull, 0ull, 0ull, 0ull};
        #pragma unroll
        for (int m = 0; m < 8; m++) {
            #pragma unroll
            for (int o = 0; o < 4; o++) dd[o] = fma2(fd[m], P[o + m], dd[o]);
        }
        #pragma unroll
        for (int o = 0; o < 4; o++) {
            int t = q0 + o;
            if (!MASK || t < hi) det[t] = hsum2(dd[o]);
        }
    }
}

// ---------------------------------------------------------------------------
// Level-2 pass: 512 outputs, 2 per thread (all 256 threads), skewed src,
// linear dst (s_a2) pre-offset by dst0.
// ---------------------------------------------------------------------------
template<bool DET, bool MASK>
__device__ __forceinline__ void l2_pass(const float* __restrict__ src,
                                        float* __restrict__ a2,
                                        float* __restrict__ det,
                                        int hi, int dqlim,
                                        const ull* fa, const ull* fd, int tid)
{
    const int q  = 2 * tid;                      // 0..510
    const int b0 = 2 * q;
    ull P[9];
    #pragma unroll
    for (int k = 0; k < 4; k++) {
        ulonglong2 v = *(const ulonglong2*)(src + MP(b0 + 4 * k));
        P[2 * k] = v.x; P[2 * k + 1] = v.y;
    }
    P[8] = *(const ull*)(src + MP(b0 + 16));

    ull a0 = 0ull, a1 = 0ull;
    #pragma unroll
    for (int m = 0; m < 8; m++) {
        a0 = fma2(fa[m], P[m],     a0);
        a1 = fma2(fa[m], P[m + 1], a1);
    }
    float ra0 = hsum2(a0), ra1 = hsum2(a1);
    if (!MASK) { a2[q] = ra0; a2[q + 1] = ra1; }
    else {
        if (q < dqlim)     a2[q]     = ra0;
        if (q + 1 < dqlim) a2[q + 1] = ra1;
    }
    if (DET) {
        ull d0 = 0ull, d1 = 0ull;
        #pragma unroll
        for (int m = 0; m < 8; m++) {
            d0 = fma2(fd[m], P[m],     d0);
            d1 = fma2(fd[m], P[m + 1], d1);
        }
        if (!MASK || q < hi)     det[q]     = hsum2(d0);
        if (!MASK || q + 1 < hi) det[q + 1] = hsum2(d1);
    }
}

// ---------------------------------------------------------------------------
// Fused 6-level DWT. Grid (SPLIT, ROWS), 256 threads.
// ---------------------------------------------------------------------------
__global__ void __launch_bounds__(256, 3)
fused_dwt_kernel(const float* __restrict__ signal, float* __restrict__ out)
{
    __shared__ __align__(16) float sm[ARENA];
    const int tid = threadIdx.x;
    const int j   = blockIdx.x;
    const int r   = blockIdx.y;
    const int n   = r & 3;
    const float* x = signal + (size_t)(r >> 2) * SIG_LEN;
    float* orow = out + (size_t)r * T_OUT;

    uint32_t smb;
    asm("{ .reg .u64 t; cvta.to.shared.u64 t, %1; cvt.u32.u64 %0, t; }"
        : "=r"(smb) : "l"(sm));

    ull fa[8], fd[8];
    {
        const ull* fap = (const ull*)g_filt[0][n];
        const ull* fdp = (const ull*)g_filt[1][n];
        #pragma unroll
        for (int m = 0; m < 8; m++) { fa[m] = __ldg(fap + m); fd[m] = __ldg(fdp + m); }
    }

    // Init zeros: L1A head (step-0 source head), s_a2 head pad + tail zeros
    if (tid < 15)               sm[OFF_L1A + tid] = 0.f;
    if (tid >= 32 && tid < 35)  sm[OFF_A2 + (tid - 32)] = 0.f;
    if (tid >= 64 && tid < 112) sm[OFF_A2 + 4608 + (tid - 64)] = 0.f;

    const int Lout[6] = {65544, 32780, 16398, 8207, 4111, 2063};
    int olo[6], ohi[6];
    #pragma unroll
    for (int l = 0; l < 6; l++) {
        int c = CHK >> (l + 1);
        olo[l] = j * c;
        ohi[l] = (j == SPLIT - 1) ? Lout[l] : (j + 1) * c;
    }
    float* gd1 = orow + 65622;  float* gd2 = orow + 32842;
    float* gd3 = orow + 16444;  float* gd4 = orow + 8237;
    float* gd5 = orow + 4126;   float* gd6 = orow + 2063;

    // Async staging into skewed s_in: s_in[MP(i)] = x[pin-15+i], i in [0,2064)
    auto stage_async = [&](int off, int pin) {
        #pragma unroll
        for (int c = 0; c < 8; c++) {
            int i  = tid + 256 * c;
            int gi = pin - 15 + i;
            bool ok = (gi >= 0) && (gi < SIG_LEN);
            const float* gp = x + (ok ? gi : 0);
            uint32_t sa = smb + (uint32_t)(off + MP(i)) * 4u;
            int sz = ok ? 4 : 0;
            asm volatile("cp.async.ca.shared.global [%0], [%1], 4, %2;"
                         :: "r"(sa), "l"(gp), "r"(sz) : "memory");
        }
        if (tid < 16) {
            int i  = tid + 2048;
            int gi = pin - 15 + i;
            bool ok = (gi >= 0) && (gi < SIG_LEN);
            const float* gp = x + (ok ? gi : 0);
            uint32_t sa = smb + (uint32_t)(off + MP(i)) * 4u;
            int sz = ok ? 4 : 0;
            asm volatile("cp.async.ca.shared.global [%0], [%1], 4, %2;"
                         :: "r"(sa), "l"(gp), "r"(sz) : "memory");
        }
    };

    // Generic masked 2-output level for the tail (linear buffers)
    auto level = [&](const float* __restrict__ src, int woff,
                     float* __restrict__ dst, int dst0,
                     float* __restrict__ det, int tg0, int lo, int hi,
                     float* __restrict__ app, int nq)
    {
        for (int q = 2 * tid; q < nq; q += 512) {
            const float* w = src + woff + 2 * q;
            ulonglong2 v0 = *(const ulonglong2*)(w);
            ulonglong2 v1 = *(const ulonglong2*)(w + 4);
            ulonglong2 v2 = *(const ulonglong2*)(w + 8);
            ulonglong2 v3 = *(const ulonglong2*)(w + 12);
            ull p8 = *(const ull*)(w + 16);
            ull P[9] = {v0.x, v0.y, v1.x, v1.y, v2.x, v2.y, v3.x, v3.y, p8};
            ull a0 = 0ull, a1 = 0ull, d0 = 0ull, d1 = 0ull;
            #pragma unroll
            for (int m = 0; m < 8; m++) {
                a0 = fma2(fa[m], P[m],     a0);
                d0 = fma2(fd[m], P[m],     d0);
                a1 = fma2(fa[m], P[m + 1], a1);
                d1 = fma2(fd[m], P[m + 1], d1);
            }
            float ra0 = hsum2(a0), ra1 = hsum2(a1);
            float rd0 = hsum2(d0), rd1 = hsum2(d1);
            if (dst) { dst[dst0 + q] = ra0; dst[dst0 + q + 1] = ra1; }
            const int t = tg0 + q;
            if (t >= lo && t < hi)     { det[t]     = rd0; if (app) app[t]     = ra0; }
            if (t+1 >= lo && t+1 < hi) { det[t + 1] = rd1; if (app) app[t + 1] = ra1; }
        }
    };

    const int base2 = j * 4096 - 512;
    const int P0    = j * CHK - SS;
    const int nstep = (j == SPLIT - 1) ? 10 : 9;

    stage_async(OFF_IN0, P0);
    asm volatile("cp.async.commit_group;" ::: "memory");

    for (int step = 0; step < nstep; step++) {
        const int pin = P0 + step * SS;
        const float* sin = sm + ((step & 1) ? OFF_IN1 : OFF_IN0);
        float* l1c = sm + ((step & 1) ? OFF_L1B : OFF_L1A);
        float* l1n = sm + ((step & 1) ? OFF_L1A : OFF_L1B);

        if (step + 1 < nstep) {
            stage_async((step & 1) ? OFF_IN0 : OFF_IN1, pin + SS);
            asm volatile("cp.async.commit_group;" ::: "memory");
            asm volatile("cp.async.wait_group 1;" ::: "memory");
        } else {
            asm volatile("cp.async.wait_group 0;" ::: "memory");
        }
        __syncthreads();

        float* d1p = gd1 + (pin >> 1);           // det1 base for this step
        if (step == 0)
            l1_pass<false, false>(sin, l1c, l1n, d1p, 0, fa, fd, tid);
        else if (step <= 8)
            l1_pass<true,  false>(sin, l1c, l1n, d1p, 0, fa, fd, tid);
        else
            l1_pass<true,  true >(sin, l1c, l1n, d1p, ohi[0] - (pin >> 1), fa, fd, tid);
        __syncthreads();

        float* a2d = sm + OFF_A2 + step * 512 + 3;
        float* d2p = gd2 + (pin >> 2);
        if (step == 0)
            l2_pass<false, false>(l1c, a2d, d2p, 0, 0, fa, fd, tid);
        else if (step <= 8)
            l2_pass<true,  false>(l1c, a2d, d2p, 0, 0, fa, fd, tid);
        else
            l2_pass<true,  true >(l1c, a2d, d2p, ohi[1] - (pin >> 2),
                                  Lout[1] - (base2 + step * 512), fa, fd, tid);
    }

    __syncthreads();
    // Zero tail-buffer pads (heads [0,3) and right-edge zero regions)
    if (tid < 3) { sm[OFF_L3 + tid] = 0.f; sm[OFF_L4 + tid] = 0.f; sm[OFF_L5 + tid] = 0.f; }
    if (tid >= 32 && tid < 63)  sm[OFF_L3 + 2177 + (tid - 32)] = 0.f;
    if (tid >= 64 && tid < 94)  sm[OFF_L4 + 1090 + (tid - 64)] = 0.f;
    if (tid >= 96 && tid < 126) sm[OFF_L5 +  546 + (tid - 96)] = 0.f;
    __syncthreads();

    // Tail: levels 3..6 once. Left halos 112/48/16 cover the dependency cone.
    {
        const int a3 = olo[2] - 112, n3 = ohi[2] - a3;      // even
        level(sm + OFF_A2, 276, sm + OFF_L3, 3,
              gd3, a3, olo[2], ohi[2], (float*)0, n3);
        __syncthreads();

        const int a4 = olo[3] - 48, n4 = ohi[3] - a4;
        level(sm + OFF_L3, 4, sm + OFF_L4, 3,
              gd4, a4, olo[3], ohi[3], (float*)0, n4);
        __syncthreads();

        const int a5 = olo[4] - 16, n5 = ohi[4] - a5;
        level(sm + OFF_L4, 4, sm + OFF_L5, 3,
              gd5, a5, olo[4], ohi[4], (float*)0, n5);
        __syncthreads();

        level(sm + OFF_L5, 4, (float*)0, 0,
              gd6, olo[5], olo[5], ohi[5], orow, ohi[5] - olo[5]);
    }
}

// ---------------------------------------------------------------------------
extern "C" void kernel_launch(void* const* d_in, const int* in_sizes, int n_in,
                              void* d_out, int out_size) {
    const float* signal = (const float*)d_in[0];
    const float* low    = (const float*)d_in[1];
    const float* high   = (const float*)d_in[2];
    float* out = (float*)d_out;

    constrain_kernel<<<1, 128>>>(low, high);

    dim3 grid(SPLIT, ROWS);
    fused_dwt_kernel<<<grid, 256>>>(signal, out);
}

// round 9
// speedup vs baseline: 1.2150x; 1.2150x over previous
#include <cuda_runtime.h>
#include <math.h>
#include <stdint.h>

// Problem constants
#define SIG_LEN   131072
#define NW        4
#define ROWS      256
#define T_OUT     131166
#define SPLIT     8
#define CHK       16384               // input samples owned per block
#define SS        2048                // input samples per scan step

typedef unsigned long long ull;

__device__ float g_filt[2][4][16];    // [lp/hp][wavelet][tap]

// ---------------------------------------------------------------------------
// Filter constraint (fp32), 512 threads: 128 taps x 4-way k-split + reduce.
// filt[j] = (1/64) sum_k src[k]*(w0 + 2*sum_{f=1..31} w_f cos(2pi f(j-k)/64)
//                                + w32 cos(pi(j-k))), then L2-normalize * sqrt2.
// ---------------------------------------------------------------------------
__global__ void __launch_bounds__(512) constrain_kernel(
        const float* __restrict__ low, const float* __restrict__ high) {
    __shared__ float ctab[64];
    __shared__ float part[512];
    __shared__ float taps[128];
    const int tid = threadIdx.x;                 // 0..511
    if (tid < 64) ctab[tid] = cosf(2.0f * (float)M_PI * (float)tid / 64.0f);
    __syncthreads();

    const int combo = tid >> 2;                  // 0..127
    const int kq    = tid & 3;                   // k quarter
    const int bank  = combo >> 6;                // 0 = lp, 1 = hp
    const int n     = (combo >> 4) & 3;          // wavelet
    const int j     = combo & 15;                // output tap
    const float* src = bank ? high : low;

    const float target = ((float)n + 0.5f) / (float)NW * 0.5f + (bank ? 0.5f : 0.0f);
    const float inv_width = (float)NW;

    float w[33];
    #pragma unroll
    for (int f = 0; f <= 32; f++) {
        float d = ((float)f / 32.0f - target) * inv_width;
        w[f] = expf(-d * d);
    }

    float acc = 0.0f;
    #pragma unroll
    for (int kk = 0; kk < 4; kk++) {
        int k  = 4 * kq + kk;
        int dm = j - k + 64;
        float c = w[0];
        #pragma unroll
        for (int f = 1; f <= 31; f++)
            c = fmaf(2.0f * w[f], ctab[(dm * f) & 63], c);
        c = fmaf(w[32], ctab[(dm * 32) & 63], c);
        acc = fmaf(src[n * 16 + k], c, acc);
    }
    part[tid] = acc;
    __syncthreads();

    if (tid < 128) {
        float tv = ((part[4 * tid] + part[4 * tid + 1]) +
                    (part[4 * tid + 2] + part[4 * tid + 3])) * (1.0f / 64.0f);
        taps[tid] = tv;
    }
    __syncthreads();

    if (tid < 128) {
        const int base = tid & ~15;
        float ss = 0.0f;
        #pragma unroll
        for (int m = 0; m < 16; m++) { float v = taps[base + m]; ss = fmaf(v, v, ss); }
        float nrm = sqrtf(ss);
        if (nrm < 1e-12f) nrm = 1e-12f;
        g_filt[tid >> 6][(tid >> 4) & 3][tid & 15] =
            taps[tid] / nrm * 1.41421356237309515f;
    }
}

// ---------------------------------------------------------------------------
__device__ __forceinline__ ull fma2(ull a, ull b, ull c) {
    ull d;
    asm("fma.rn.f32x2 %0, %1, %2, %3;" : "=l"(d) : "l"(a), "l"(b), "l"(c));
    return d;
}
__device__ __forceinline__ float hsum2(ull a) {
    float2 v = *reinterpret_cast<float2*>(&a);
    return v.x + v.y;
}

// Shared-memory arena (floats). Step phase: s_in0, s_in1, s_l1, s_a2.
// Tail phase overlays s_l3/l4/l5 on the s_in region. s_a2 persists.
#define OFF_IN0 0      // 2080 floats
#define OFF_IN1 2080   // 2080 floats
#define OFF_L1  4160   // 1056 floats (15 carry + 1024)
#define OFF_L3  0      // 2208 floats (tail overlay)
#define OFF_L4  2208   // 1120 floats
#define OFF_L5  3328   // 576 floats
#define OFF_A2  5216   // 4656 floats (l2 approx: chunk + halo, +3 shift)
#define ARENA   9872

// ---------------------------------------------------------------------------
// Fused 6-level DWT. Grid (SPLIT, ROWS), 256 threads, 4 blocks/SM target.
// Step loop (double-buffered cp.async staging): stage s+1, level1, level2.
// Tail: levels 3..6 once over the chunk (+ left halo cone 112/48/16).
// Conv: out[t] = sum_k f[k] x[2t+k-15]; window q -> src[woff+2q .. +17],
// per-thread bases multiples of 4 floats (16B-aligned LDS.128).
// ---------------------------------------------------------------------------
__global__ void __launch_bounds__(256, 4)
fused_dwt_kernel(const float* __restrict__ signal, float* __restrict__ out)
{
    __shared__ __align__(16) float sm[ARENA];
    const int tid = threadIdx.x;
    const int j   = blockIdx.x;
    const int r   = blockIdx.y;
    const int n   = r & 3;
    const float* x = signal + (size_t)(r >> 2) * SIG_LEN;
    float* orow = out + (size_t)r * T_OUT;

    uint32_t smb;
    asm("{ .reg .u64 t; cvta.to.shared.u64 t, %1; cvt.u32.u64 %0, t; }"
        : "=r"(smb) : "l"(sm));

    ull fa[8], fd[8];
    {
        const ull* fap = (const ull*)g_filt[0][n];
        const ull* fdp = (const ull*)g_filt[1][n];
        #pragma unroll
        for (int m = 0; m < 8; m++) { fa[m] = __ldg(fap + m); fd[m] = __ldg(fdp + m); }
    }

    // Init zeros: s_l1 tail (first carry source), s_a2 head pad + tail zeros
    if (tid < 15)               sm[OFF_L1 + 1024 + tid] = 0.f;
    if (tid >= 32 && tid < 35)  sm[OFF_A2 + (tid - 32)] = 0.f;
    if (tid >= 64 && tid < 112) sm[OFF_A2 + 4608 + (tid - 64)] = 0.f;

    const int Lout[6] = {65544, 32780, 16398, 8207, 4111, 2063};
    int olo[6], ohi[6];
    #pragma unroll
    for (int l = 0; l < 6; l++) {
        int c = CHK >> (l + 1);
        olo[l] = j * c;
        ohi[l] = (j == SPLIT - 1) ? Lout[l] : (j + 1) * c;
    }
    float* gd1 = orow + 65622;  float* gd2 = orow + 32842;
    float* gd3 = orow + 16444;  float* gd4 = orow + 8237;
    float* gd5 = orow + 4126;   float* gd6 = orow + 2063;

    // Async staging: s_in[buf][i] = x[pin-15+i], i in [0, 2064); zero-filled OOB.
    auto stage_async = [&](int off, int pin) {
        #pragma unroll
        for (int c = 0; c < 8; c++) {
            int i  = tid + 256 * c;
            int gi = pin - 15 + i;
            bool ok = (gi >= 0) && (gi < SIG_LEN);
            const float* gp = x + (ok ? gi : 0);
            uint32_t sa = smb + (uint32_t)(off + i) * 4u;
            int sz = ok ? 4 : 0;
            asm volatile("cp.async.ca.shared.global [%0], [%1], 4, %2;"
                         :: "r"(sa), "l"(gp), "r"(sz) : "memory");
        }
        if (tid < 16) {
            int i  = tid + 2048;
            int gi = pin - 15 + i;
            bool ok = (gi >= 0) && (gi < SIG_LEN);
            const float* gp = x + (ok ? gi : 0);
            uint32_t sa = smb + (uint32_t)(off + i) * 4u;
            int sz = ok ? 4 : 0;
            asm volatile("cp.async.ca.shared.global [%0], [%1], 4, %2;"
                         :: "r"(sa), "l"(gp), "r"(sz) : "memory");
        }
    };

    // Generic masked 2-output level (linear buffers, both filters)
    auto level = [&](const float* __restrict__ src, int woff,
                     float* __restrict__ dst, int dst0, int dqlim,
                     float* __restrict__ det, int tg0, int lo, int hi,
                     float* __restrict__ app, int nq)
    {
        for (int q = 2 * tid; q < nq; q += 512) {
            const float* w = src + woff + 2 * q;
            ulonglong2 v0 = *(const ulonglong2*)(w);
            ulonglong2 v1 = *(const ulonglong2*)(w + 4);
            ulonglong2 v2 = *(const ulonglong2*)(w + 8);
            ulonglong2 v3 = *(const ulonglong2*)(w + 12);
            ull p8 = *(const ull*)(w + 16);
            ull P[9] = {v0.x, v0.y, v1.x, v1.y, v2.x, v2.y, v3.x, v3.y, p8};
            ull a0 = 0ull, a1 = 0ull, d0 = 0ull, d1 = 0ull;
            #pragma unroll
            for (int m = 0; m < 8; m++) {
                a0 = fma2(fa[m], P[m],     a0);
                d0 = fma2(fd[m], P[m],     d0);
                a1 = fma2(fa[m], P[m + 1], a1);
                d1 = fma2(fd[m], P[m + 1], d1);
            }
            float ra0 = hsum2(a0), ra1 = hsum2(a1);
            float rd0 = hsum2(d0), rd1 = hsum2(d1);
            if (dst) {
                if (q < dqlim)     dst[dst0 + q]     = ra0;
                if (q + 1 < dqlim) dst[dst0 + q + 1] = ra1;
            }
            const int t = tg0 + q;
            if (t >= lo && t < hi)     { det[t]     = rd0; if (app) app[t]     = ra0; }
            if (t+1 >= lo && t+1 < hi) { det[t + 1] = rd1; if (app) app[t + 1] = ra1; }
        }
    };

    const int base2 = j * 4096 - 512;
    const int P0    = j * CHK - SS;
    const int nstep = (j == SPLIT - 1) ? 10 : 9;

    stage_async(OFF_IN0, P0);
    asm volatile("cp.async.commit_group;" ::: "memory");

    for (int step = 0; step < nstep; step++) {
        const int pin  = P0 + step * SS;
        const int cbuf = (step & 1) ? OFF_IN1 : OFF_IN0;
        const int nbuf = (step & 1) ? OFF_IN0 : OFF_IN1;
        __syncthreads();                         // prev L1/L2 reads done

        // Carry s_l1 head <- old tail; prefetch next step; wait current.
        if (tid < 15) sm[OFF_L1 + tid] = sm[OFF_L1 + 1024 + tid];
        if (step + 1 < nstep) {
            stage_async(nbuf, pin + SS);
            asm volatile("cp.async.commit_group;" ::: "memory");
            asm volatile("cp.async.wait_group 1;" ::: "memory");
        } else {
            asm volatile("cp.async.wait_group 0;" ::: "memory");
        }
        __syncthreads();

        // Level 1: 1024 outputs at u = (pin>>1)+q; approx -> s_l1[15+q]
        level(sm + cbuf, 0, sm + OFF_L1, 15, 1 << 30,
              gd1, pin >> 1, olo[0], ohi[0], (float*)0, 1024);
        __syncthreads();

        // Level 2: 512 outputs at u2 = (pin>>2)+q; approx -> s_a2[step*512+3+q]
        level(sm + OFF_L1, 0, sm + OFF_A2, step * 512 + 3,
              Lout[1] - (base2 + step * 512),
              gd2, pin >> 2, olo[1], ohi[1], (float*)0, 512);
    }

    __syncthreads();
    // Zero tail-buffer pads (heads [0,3) and right-edge zero regions)
    if (tid < 3) { sm[OFF_L3 + tid] = 0.f; sm[OFF_L4 + tid] = 0.f; sm[OFF_L5 + tid] = 0.f; }
    if (tid >= 32 && tid < 63)  sm[OFF_L3 + 2177 + (tid - 32)] = 0.f;
    if (tid >= 64 && tid < 94)  sm[OFF_L4 + 1090 + (tid - 64)] = 0.f;
    if (tid >= 96 && tid < 126) sm[OFF_L5 +  546 + (tid - 96)] = 0.f;
    __syncthreads();

    // Tail: levels 3..6 once. Left halos 112/48/16 cover the dependency cone.
    {
        const int a3 = olo[2] - 112, n3 = ohi[2] - a3;      // even
        level(sm + OFF_A2, 276, sm + OFF_L3, 3, 1 << 30,
              gd3, a3, olo[2], ohi[2], (float*)0, n3);
        __syncthreads();

        const int a4 = olo[3] - 48, n4 = ohi[3] - a4;
        level(sm + OFF_L3, 4, sm + OFF_L4, 3, 1 << 30,
              gd4, a4, olo[3], ohi[3], (float*)0, n4);
        __syncthreads();

        const int a5 = olo[4] - 16, n5 = ohi[4] - a5;
        level(sm + OFF_L4, 4, sm + OFF_L5, 3, 1 << 30,
              gd5, a5, olo[4], ohi[4], (float*)0, n5);
        __syncthreads();

        level(sm + OFF_L5, 4, (float*)0, 0, 0,
              gd6, olo[5], olo[5], ohi[5], orow, ohi[5] - olo[5]);
    }
}

// ---------------------------------------------------------------------------
extern "C" void kernel_launch(void* const* d_in, const int* in_sizes, int n_in,
                              void* d_out, int out_size) {
    const float* signal = (const float*)d_in[0];
    const float* low    = (const float*)d_in[1];
    const float* high   = (const float*)d_in[2];
    float* out = (float*)d_out;

    constrain_kernel<<<1, 512>>>(low, high);

    dim3 grid(SPLIT, ROWS);
    fused_dwt_kernel<<<grid, 256>>>(signal, out);
}

// round 10
// speedup vs baseline: 1.2931x; 1.0642x over previous
#include <cuda_runtime.h>
#include <math.h>
#include <stdint.h>

// Problem constants
#define SIG_LEN   131072
#define NW        4
#define ROWS      256
#define T_OUT     131166
#define SPLIT     8
#define CHK       16384               // input samples owned per block
#define SS        2048                // input samples per scan step

typedef unsigned long long ull;

__device__ float g_filt[2][4][16];    // [lp/hp][wavelet][tap]

// ---------------------------------------------------------------------------
// Filter constraint (fp32), 512 threads: 128 taps x 4-way k-split + reduce.
// ---------------------------------------------------------------------------
__global__ void __launch_bounds__(512) constrain_kernel(
        const float* __restrict__ low, const float* __restrict__ high) {
    __shared__ float ctab[64];
    __shared__ float part[512];
    __shared__ float taps[128];
    const int tid = threadIdx.x;                 // 0..511
    if (tid < 64) ctab[tid] = cosf(2.0f * (float)M_PI * (float)tid / 64.0f);
    __syncthreads();

    const int combo = tid >> 2;                  // 0..127
    const int kq    = tid & 3;                   // k quarter
    const int bank  = combo >> 6;                // 0 = lp, 1 = hp
    const int n     = (combo >> 4) & 3;          // wavelet
    const int j     = combo & 15;                // output tap
    const float* src = bank ? high : low;

    const float target = ((float)n + 0.5f) / (float)NW * 0.5f + (bank ? 0.5f : 0.0f);
    const float inv_width = (float)NW;

    float w[33];
    #pragma unroll
    for (int f = 0; f <= 32; f++) {
        float d = ((float)f / 32.0f - target) * inv_width;
        w[f] = expf(-d * d);
    }

    float acc = 0.0f;
    #pragma unroll
    for (int kk = 0; kk < 4; kk++) {
        int k  = 4 * kq + kk;
        int dm = j - k + 64;
        float c = w[0];
        #pragma unroll
        for (int f = 1; f <= 31; f++)
            c = fmaf(2.0f * w[f], ctab[(dm * f) & 63], c);
        c = fmaf(w[32], ctab[(dm * 32) & 63], c);
        acc = fmaf(src[n * 16 + k], c, acc);
    }
    part[tid] = acc;
    __syncthreads();

    if (tid < 128) {
        float tv = ((part[4 * tid] + part[4 * tid + 1]) +
                    (part[4 * tid + 2] + part[4 * tid + 3])) * (1.0f / 64.0f);
        taps[tid] = tv;
    }
    __syncthreads();

    if (tid < 128) {
        const int base = tid & ~15;
        float ss = 0.0f;
        #pragma unroll
        for (int m = 0; m < 16; m++) { float v = taps[base + m]; ss = fmaf(v, v, ss); }
        float nrm = sqrtf(ss);
        if (nrm < 1e-12f) nrm = 1e-12f;
        g_filt[tid >> 6][(tid >> 4) & 3][tid & 15] =
            taps[tid] / nrm * 1.41421356237309515f;
    }
}

// ---------------------------------------------------------------------------
__device__ __forceinline__ ull fma2(ull a, ull b, ull c) {
    ull d;
    asm("fma.rn.f32x2 %0, %1, %2, %3;" : "=l"(d) : "l"(a), "l"(b), "l"(c));
    return d;
}
__device__ __forceinline__ float hsum2(ull a) {
    float2 v = *reinterpret_cast<float2*>(&a);
    return v.x + v.y;
}

// Shared-memory arena (floats). Step phase: s_in0, s_in1, s_l1, s_a2.
// Tail phase overlays s_l3/l4/l5 on the s_in region. s_a2 persists.
#define OFF_IN0 0      // 2080 floats
#define OFF_IN1 2080   // 2080 floats
#define OFF_L1  4160   // 1056 floats (15 carry + 1024)
#define OFF_L3  0      // 2208 floats (tail overlay)
#define OFF_L4  2208   // 1120 floats
#define OFF_L5  3328   // 576 floats
#define OFF_A2  5216   // 4656 floats (l2 approx: chunk + halo, +3 shift)
#define ARENA   9872

// ---------------------------------------------------------------------------
// Staging: s_in[i] = x[pin-15+i], i in [0, 2064). CHECK=false -> bare cp.async.
// ---------------------------------------------------------------------------
template<bool CHECK>
__device__ __forceinline__ void stage(uint32_t smb, const float* __restrict__ x,
                                      int off, int pin, int tid)
{
    #pragma unroll
    for (int c = 0; c < 9; c++) {
        int i = tid + 256 * c;
        if (c == 8 && tid >= 16) break;
        int gi = pin - 15 + i;
        uint32_t sa = smb + (uint32_t)(off + i) * 4u;
        if (CHECK) {
            bool ok = (gi >= 0) && (gi < SIG_LEN);
            const float* gp = x + (ok ? gi : 0);
            int sz = ok ? 4 : 0;
            asm volatile("cp.async.ca.shared.global [%0], [%1], 4, %2;"
                         :: "r"(sa), "l"(gp), "r"(sz) : "memory");
        } else {
            const float* gp = x + gi;
            asm volatile("cp.async.ca.shared.global [%0], [%1], 4;"
                         :: "r"(sa), "l"(gp) : "memory");
        }
    }
}

// ---------------------------------------------------------------------------
// Level-1 pass: 1024 outputs, 2/thread x 2 iters. Window q = src[2q..2q+17].
// Approx -> dst[15+q]; detail -> det[q] (float2 when unmasked).
// ---------------------------------------------------------------------------
template<bool DET, bool MASK>
__device__ __forceinline__ void l1_pass(const float* __restrict__ src,
                                        float* __restrict__ dst,
                                        float* __restrict__ det, int hi,
                                        const ull* fa, const ull* fd, int tid)
{
    #pragma unroll
    for (int it = 0; it < 2; it++) {
        const int q = 2 * tid + 512 * it;
        const float* w = src + 2 * q;
        ulonglong2 v0 = *(const ulonglong2*)(w);
        ulonglong2 v1 = *(const ulonglong2*)(w + 4);
        ulonglong2 v2 = *(const ulonglong2*)(w + 8);
        ulonglong2 v3 = *(const ulonglong2*)(w + 12);
        ull p8 = *(const ull*)(w + 16);
        ull P[9] = {v0.x, v0.y, v1.x, v1.y, v2.x, v2.y, v3.x, v3.y, p8};
        ull a0 = 0ull, a1 = 0ull;
        #pragma unroll
        for (int m = 0; m < 8; m++) {
            a0 = fma2(fa[m], P[m],     a0);
            a1 = fma2(fa[m], P[m + 1], a1);
        }
        dst[15 + q] = hsum2(a0);
        dst[16 + q] = hsum2(a1);
        if (DET) {
            ull d0 = 0ull, d1 = 0ull;
            #pragma unroll
            for (int m = 0; m < 8; m++) {
                d0 = fma2(fd[m], P[m],     d0);
                d1 = fma2(fd[m], P[m + 1], d1);
            }
            float rd0 = hsum2(d0), rd1 = hsum2(d1);
            if (!MASK) {
                *reinterpret_cast<float2*>(det + q) = make_float2(rd0, rd1);
            } else {
                if (q < hi)     det[q]     = rd0;
                if (q + 1 < hi) det[q + 1] = rd1;
            }
        }
    }
}

// ---------------------------------------------------------------------------
// Level-2 pass: 512 outputs, 2/thread, one iter. Window q = src[2q..2q+17].
// Approx -> a2[q] (pre-offset, dqlim-masked only when MASK); detail -> det[q].
// ---------------------------------------------------------------------------
template<bool DET, bool MASK>
__device__ __forceinline__ void l2_pass(const float* __restrict__ src,
                                        float* __restrict__ a2,
                                        float* __restrict__ det,
                                        int hi, int dqlim,
                                        const ull* fa, const ull* fd, int tid)
{
    const int q = 2 * tid;
    const float* w = src + 2 * q;
    ulonglong2 v0 = *(const ulonglong2*)(w);
    ulonglong2 v1 = *(const ulonglong2*)(w + 4);
    ulonglong2 v2 = *(const ulonglong2*)(w + 8);
    ulonglong2 v3 = *(const ulonglong2*)(w + 12);
    ull p8 = *(const ull*)(w + 16);
    ull P[9] = {v0.x, v0.y, v1.x, v1.y, v2.x, v2.y, v3.x, v3.y, p8};
    ull a0 = 0ull, a1 = 0ull;
    #pragma unroll
    for (int m = 0; m < 8; m++) {
        a0 = fma2(fa[m], P[m],     a0);
        a1 = fma2(fa[m], P[m + 1], a1);
    }
    float ra0 = hsum2(a0), ra1 = hsum2(a1);
    if (!MASK) { a2[q] = ra0; a2[q + 1] = ra1; }
    else {
        if (q < dqlim)     a2[q]     = ra0;
        if (q + 1 < dqlim) a2[q + 1] = ra1;
    }
    if (DET) {
        ull d0 = 0ull, d1 = 0ull;
        #pragma unroll
        for (int m = 0; m < 8; m++) {
            d0 = fma2(fd[m], P[m],     d0);
            d1 = fma2(fd[m], P[m + 1], d1);
        }
        float rd0 = hsum2(d0), rd1 = hsum2(d1);
        if (!MASK) {
            *reinterpret_cast<float2*>(det + q) = make_float2(rd0, rd1);
        } else {
            if (q < hi)     det[q]     = rd0;
            if (q + 1 < hi) det[q + 1] = rd1;
        }
    }
}

// ---------------------------------------------------------------------------
// Fused 6-level DWT. Grid (SPLIT, ROWS), 256 threads, 4 blocks/SM.
// ---------------------------------------------------------------------------
__global__ void __launch_bounds__(256, 4)
fused_dwt_kernel(const float* __restrict__ signal, float* __restrict__ out)
{
    __shared__ __align__(16) float sm[ARENA];
    const int tid = threadIdx.x;
    const int j   = blockIdx.x;
    const int r   = blockIdx.y;
    const int n   = r & 3;
    const float* x = signal + (size_t)(r >> 2) * SIG_LEN;
    float* orow = out + (size_t)r * T_OUT;

    uint32_t smb;
    asm("{ .reg .u64 t; cvta.to.shared.u64 t, %1; cvt.u32.u64 %0, t; }"
        : "=r"(smb) : "l"(sm));

    ull fa[8], fd[8];
    {
        const ull* fap = (const ull*)g_filt[0][n];
        const ull* fdp = (const ull*)g_filt[1][n];
        #pragma unroll
        for (int m = 0; m < 8; m++) { fa[m] = __ldg(fap + m); fd[m] = __ldg(fdp + m); }
    }

    // Init zeros: s_l1 tail (first carry source), s_a2 head pad + tail zeros
    if (tid < 15)               sm[OFF_L1 + 1024 + tid] = 0.f;
    if (tid >= 32 && tid < 35)  sm[OFF_A2 + (tid - 32)] = 0.f;
    if (tid >= 64 && tid < 112) sm[OFF_A2 + 4608 + (tid - 64)] = 0.f;

    const int Lout[6] = {65544, 32780, 16398, 8207, 4111, 2063};
    int olo[6], ohi[6];
    #pragma unroll
    for (int l = 0; l < 6; l++) {
        int c = CHK >> (l + 1);
        olo[l] = j * c;
        ohi[l] = (j == SPLIT - 1) ? Lout[l] : (j + 1) * c;
    }
    float* gd1 = orow + 65622;  float* gd2 = orow + 32842;
    float* gd3 = orow + 16444;  float* gd4 = orow + 8237;
    float* gd5 = orow + 4126;   float* gd6 = orow + 2063;

    // Generic masked 2-output level (tail levels 3..6)
    auto level = [&](const float* __restrict__ src, int woff,
                     float* __restrict__ dst, int dst0,
                     float* __restrict__ det, int tg0, int lo, int hi,
                     float* __restrict__ app, int nq)
    {
        for (int q = 2 * tid; q < nq; q += 512) {
            const float* w = src + woff + 2 * q;
            ulonglong2 v0 = *(const ulonglong2*)(w);
            ulonglong2 v1 = *(const ulonglong2*)(w + 4);
            ulonglong2 v2 = *(const ulonglong2*)(w + 8);
            ulonglong2 v3 = *(const ulonglong2*)(w + 12);
            ull p8 = *(const ull*)(w + 16);
            ull P[9] = {v0.x, v0.y, v1.x, v1.y, v2.x, v2.y, v3.x, v3.y, p8};
            ull a0 = 0ull, a1 = 0ull, d0 = 0ull, d1 = 0ull;
            #pragma unroll
            for (int m = 0; m < 8; m++) {
                a0 = fma2(fa[m], P[m],     a0);
                d0 = fma2(fd[m], P[m],     d0);
                a1 = fma2(fa[m], P[m + 1], a1);
                d1 = fma2(fd[m], P[m + 1], d1);
            }
            float ra0 = hsum2(a0), ra1 = hsum2(a1);
            float rd0 = hsum2(d0), rd1 = hsum2(d1);
            if (dst) { dst[dst0 + q] = ra0; dst[dst0 + q + 1] = ra1; }
            const int t = tg0 + q;
            if (t >= lo && t < hi)     { det[t]     = rd0; if (app) app[t]     = ra0; }
            if (t+1 >= lo && t+1 < hi) { det[t + 1] = rd1; if (app) app[t + 1] = ra1; }
        }
    };

    const int base2 = j * 4096 - 512;
    const int P0    = j * CHK - SS;
    const int nstep = (j == SPLIT - 1) ? 10 : 9;

    // Prologue staging (step 0 buffer); edges always need CHECK here for j=0.
    if (P0 >= 2048) stage<false>(smb, x, OFF_IN0, P0, tid);
    else            stage<true >(smb, x, OFF_IN0, P0, tid);
    asm volatile("cp.async.commit_group;" ::: "memory");

    for (int step = 0; step < nstep; step++) {
        const int pin  = P0 + step * SS;
        const int cbuf = (step & 1) ? OFF_IN1 : OFF_IN0;
        const int nbuf = (step & 1) ? OFF_IN0 : OFF_IN1;
        __syncthreads();                         // prev L1/L2 reads done

        // Carry s_l1 head <- old tail; prefetch next step; wait current.
        if (tid < 15) sm[OFF_L1 + tid] = sm[OFF_L1 + 1024 + tid];
        if (step + 1 < nstep) {
            const int np = pin + SS;
            if (np >= 2048 && np < 129024) stage<false>(smb, x, nbuf, np, tid);
            else                           stage<true >(smb, x, nbuf, np, tid);
            asm volatile("cp.async.commit_group;" ::: "memory");
            asm volatile("cp.async.wait_group 1;" ::: "memory");
        } else {
            asm volatile("cp.async.wait_group 0;" ::: "memory");
        }
        __syncthreads();

        // Level 1: 1024 outputs at t = (pin>>1)+q; approx -> s_l1[15+q]
        float* d1p = gd1 + (pin >> 1);
        if (step == 0)
            l1_pass<false, false>(sm + cbuf, sm + OFF_L1, d1p, 0, fa, fd, tid);
        else if (step <= 8)
            l1_pass<true,  false>(sm + cbuf, sm + OFF_L1, d1p, 0, fa, fd, tid);
        else
            l1_pass<true,  true >(sm + cbuf, sm + OFF_L1, d1p,
                                  ohi[0] - (pin >> 1), fa, fd, tid);
        __syncthreads();

        // Level 2: 512 outputs at t = (pin>>2)+q; approx -> s_a2[step*512+3+q]
        float* a2d = sm + OFF_A2 + step * 512 + 3;
        float* d2p = gd2 + (pin >> 2);
        if (step == 0)
            l2_pass<false, false>(sm + OFF_L1, a2d, d2p, 0, 0, fa, fd, tid);
        else if (step <= 8)
            l2_pass<true,  false>(sm + OFF_L1, a2d, d2p, 0, 0, fa, fd, tid);
        else
            l2_pass<true,  true >(sm + OFF_L1, a2d, d2p,
                                  ohi[1] - (pin >> 2),
                                  Lout[1] - (base2 + step * 512), fa, fd, tid);
    }

    __syncthreads();
    // Zero tail-buffer pads (heads [0,3) and right-edge zero regions)
    if (tid < 3) { sm[OFF_L3 + tid] = 0.f; sm[OFF_L4 + tid] = 0.f; sm[OFF_L5 + tid] = 0.f; }
    if (tid >= 32 && tid < 63)  sm[OFF_L3 + 2177 + (tid - 32)] = 0.f;
    if (tid >= 64 && tid < 94)  sm[OFF_L4 + 1090 + (tid - 64)] = 0.f;
    if (tid >= 96 && tid < 126) sm[OFF_L5 +  546 + (tid - 96)] = 0.f;
    __syncthreads();

    // Tail: levels 3..6 once. Left halos 112/48/16 cover the dependency cone.
    {
        const int a3 = olo[2] - 112, n3 = ohi[2] - a3;      // even
        level(sm + OFF_A2, 276, sm + OFF_L3, 3,
              gd3, a3, olo[2], ohi[2], (float*)0, n3);
        __syncthreads();

        const int a4 = olo[3] - 48, n4 = ohi[3] - a4;
        level(sm + OFF_L3, 4, sm + OFF_L4, 3,
              gd4, a4, olo[3], ohi[3], (float*)0, n4);
        __syncthreads();

        const int a5 = olo[4] - 16, n5 = ohi[4] - a5;
        level(sm + OFF_L4, 4, sm + OFF_L5, 3,
              gd5, a5, olo[4], ohi[4], (float*)0, n5);
        __syncthreads();

        level(sm + OFF_L5, 4, (float*)0, 0,
              gd6, olo[5], olo[5], ohi[5], orow, ohi[5] - olo[5]);
    }
}

// ---------------------------------------------------------------------------
extern "C" void kernel_launch(void* const* d_in, const int* in_sizes, int n_in,
                              void* d_out, int out_size) {
    const float* signal = (const float*)d_in[0];
    const float* low    = (const float*)d_in[1];
    const float* high   = (const float*)d_in[2];
    float* out = (float*)d_out;

    constrain_kernel<<<1, 512>>>(low, high);

    dim3 grid(SPLIT, ROWS);
    fused_dwt_kernel<<<grid, 256>>>(signal, out);
}